// round 16
// baseline (speedup 1.0000x reference)
#include <cuda_runtime.h>
#include <cuda_fp16.h>
#include <cstdint>

// ---------------------------------------------------------------------------
// GAT layer. Fixed shapes: N=50000, E=800000, IN=256, H=4, F=64, HF=256
// Stream 0 : gemm (cp.async double-buffered, in-register tf32 cvt for A and B,
//            fused s_src/s_trg epilogue, proj stored fp16)
//            -> [wait CSR] -> agg (fused exp + softmax + skip + bias + leaky)
// Stream 2 : memset(deg) -> count -> scan -> scatter      (hidden under GEMM)
// ---------------------------------------------------------------------------

#define N_NODES 50000
#define N_EDGES 800000
#define IN_DIM  256
#define H       4
#define F       64
#define HF      256
#define NEG     0.2f

// -------- scratch (static device globals; allocation-free) -----------------
__device__ __half g_projh [N_NODES * HF];    // 25.6 MB, L2-resident in agg
__device__ float  g_ssrc  [N_NODES * H];
__device__ float  g_strg  [N_NODES * H];
__device__ int    g_deg   [N_NODES];
__device__ int    g_off   [N_NODES + 1];
__device__ int    g_off2  [N_NODES];         // scatter cursor (starts = g_off)
__device__ int    g_csr_src[N_EDGES];

__device__ __forceinline__ unsigned f2tf32(float x) {
    unsigned r;
    asm("cvt.rna.tf32.f32 %0, %1;" : "=r"(r) : "f"(x));
    return r;
}

__device__ __forceinline__ uint32_t s2u(const void* p) {
    uint32_t a;
    asm("{ .reg .u64 t; cvta.to.shared.u64 t, %1; cvt.u32.u64 %0, t; }"
        : "=r"(a) : "l"(p));
    return a;
}

__device__ __forceinline__ void cp16(uint32_t dst, const void* src, int bytes) {
    asm volatile("cp.async.cg.shared.global [%0], [%1], 16, %2;"
                 :: "r"(dst), "l"(src), "r"(bytes));
}

__device__ __forceinline__ void mma_tf32(float* c,
                                         unsigned a0, unsigned a1,
                                         unsigned a2, unsigned a3,
                                         unsigned b0, unsigned b1) {
    asm volatile(
        "mma.sync.aligned.m16n8k8.row.col.f32.tf32.tf32.f32 "
        "{%0,%1,%2,%3}, {%4,%5,%6,%7}, {%8,%9}, {%0,%1,%2,%3};"
        : "+f"(c[0]), "+f"(c[1]), "+f"(c[2]), "+f"(c[3])
        : "r"(a0), "r"(a1), "r"(a2), "r"(a3), "r"(b0), "r"(b1));
}

// -------- CSR build ---------------------------------------------------------
__global__ void __launch_bounds__(256)
count_kernel(const int* __restrict__ etrg) {
    int i = blockIdx.x * blockDim.x + threadIdx.x;
    if (i < N_EDGES) atomicAdd(&g_deg[etrg[i]], 1);
}

#define SCAN_T 1024
#define CHUNK  49
__global__ void __launch_bounds__(SCAN_T)
scan_kernel() {
    __shared__ int sm[SCAN_T];
    int t   = threadIdx.x;
    int beg = t * CHUNK;
    int end = min(beg + CHUNK, N_NODES);
    int s = 0;
    for (int i = beg; i < end; i++) s += g_deg[i];
    sm[t] = s;
    __syncthreads();
    for (int o = 1; o < SCAN_T; o <<= 1) {
        int v = (t >= o) ? sm[t - o] : 0;
        __syncthreads();
        if (t >= o) sm[t] += v;
        __syncthreads();
    }
    int base = (t > 0) ? sm[t - 1] : 0;
    for (int i = beg; i < end; i++) {
        g_off[i] = base; g_off2[i] = base; base += g_deg[i];
    }
    if (t == 0) g_off[N_NODES] = sm[SCAN_T - 1];
}

__global__ void __launch_bounds__(256)
scatter_kernel(const int* __restrict__ esrc, const int* __restrict__ etrg) {
    int i = blockIdx.x * blockDim.x + threadIdx.x;
    if (i >= N_EDGES) return;
    int pos = atomicAdd(&g_off2[etrg[i]], 1);
    g_csr_src[pos] = esrc[i];
}

// -------- TF32 MMA GEMM, cp.async double-buffered ---------------------------
// 1D grid, bid = bx*4 + y; y selects {W/proj-half0, W/proj-half1, skip, skip}.
// Adjacent y's share the same A tile -> 4x L2 reuse of x rows.
// A and B staged raw fp32; tf32 conversion happens at fragment load.
// proj path stores fp16 to g_projh and reduces s_src/s_trg from acc regs.
#define AS(p,m,k) As[(p)*4608 + (m)*36 + (k)]
#define BS(p,k,n) Bs[(p)*4352 + (k)*136 + (n)]
#define GEMM_SMEM ((2*4608 + 2*4352) * 4)

__global__ void __launch_bounds__(256, 2)
gemm_tf32_kernel(const float* __restrict__ A,
                 const float* __restrict__ W, const float* __restrict__ SW,
                 float* __restrict__ outC,
                 const float* __restrict__ a_src, const float* __restrict__ a_trg,
                 int M) {
    extern __shared__ float smf[];
    float* As = smf;
    float* Bs = smf + 2 * 4608;

    const int  y       = blockIdx.x & 3;
    const bool is_proj = (y < 2);
    const float* B  = is_proj ? W : SW;
    const int n0 = (y & 1) * 128;
    const int m0 = (blockIdx.x >> 2) * 128;

    const int t    = threadIdx.x;
    const int lane = t & 31;
    const int w    = t >> 5;
    const int wm   = (w & 3) * 32;
    const int wn   = (w >> 2) * 64;
    const int lr   = lane >> 2;
    const int lc   = lane & 3;

    float acc[2][8][4];
#pragma unroll
    for (int mt = 0; mt < 2; mt++)
#pragma unroll
        for (int nt = 0; nt < 8; nt++)
#pragma unroll
            for (int i = 0; i < 4; i++) acc[mt][nt][i] = 0.0f;

    // staging coords
    const int ar  = t >> 1;          // A row 0..127
    const int ac  = (t & 1) * 16;    // A k-offset
    const int br  = t >> 3;          // B k row 0..31
    const int bc0 = (t & 7) * 4;     // B n-offset, +32 strides

    const int      gm    = m0 + ar;
    const int      abyt  = (gm < M) ? 16 : 0;
    const float*   agp   = A + (size_t)gm * IN_DIM + ac;
    const uint32_t asm_b = s2u(&AS(0, ar, ac));
    const float*   bgp   = B + (size_t)br * 256 + n0 + bc0;
    const uint32_t bsm_b = s2u(&BS(0, br, bc0));

    // prologue: stage k0=0 into buffer 0
#pragma unroll
    for (int j = 0; j < 4; j++) cp16(asm_b + j * 16, agp + j * 4, abyt);
#pragma unroll
    for (int j = 0; j < 4; j++) cp16(bsm_b + j * 128, bgp + j * 32, 16);
    asm volatile("cp.async.commit_group;");

    int p = 0;
    for (int it = 0; it < 8; it++) {
        if (it < 7) {
            int k0 = (it + 1) * 32;
            uint32_t ad = asm_b + (p ^ 1) * 4608 * 4;
            uint32_t bd = bsm_b + (p ^ 1) * 4352 * 4;
#pragma unroll
            for (int j = 0; j < 4; j++) cp16(ad + j * 16,  agp + k0 + j * 4, abyt);
#pragma unroll
            for (int j = 0; j < 4; j++) cp16(bd + j * 128, bgp + (size_t)k0 * 256 + j * 32, 16);
            asm volatile("cp.async.commit_group;");
            asm volatile("cp.async.wait_group %0;" :: "n"(1));
        } else {
            asm volatile("cp.async.wait_group %0;" :: "n"(0));
        }
        __syncthreads();

#pragma unroll
        for (int kk = 0; kk < 32; kk += 8) {
            unsigned af[2][4], bf[8][2];
#pragma unroll
            for (int mt = 0; mt < 2; mt++) {
                int mb = wm + mt * 16;
                af[mt][0] = f2tf32(AS(p, mb + lr,     kk + lc));
                af[mt][1] = f2tf32(AS(p, mb + lr + 8, kk + lc));
                af[mt][2] = f2tf32(AS(p, mb + lr,     kk + lc + 4));
                af[mt][3] = f2tf32(AS(p, mb + lr + 8, kk + lc + 4));
            }
#pragma unroll
            for (int nt = 0; nt < 8; nt++) {
                int nb = wn + nt * 8 + lr;
                bf[nt][0] = f2tf32(BS(p, kk + lc,     nb));
                bf[nt][1] = f2tf32(BS(p, kk + lc + 4, nb));
            }
#pragma unroll
            for (int mt = 0; mt < 2; mt++)
#pragma unroll
                for (int nt = 0; nt < 8; nt++)
                    mma_tf32(acc[mt][nt],
                             af[mt][0], af[mt][1], af[mt][2], af[mt][3],
                             bf[nt][0], bf[nt][1]);
        }
        __syncthreads();
        p ^= 1;
    }

    // ---- store C ----
    if (is_proj) {
#pragma unroll
        for (int mt = 0; mt < 2; mt++) {
#pragma unroll
            for (int nt = 0; nt < 8; nt++) {
                int col  = n0 + wn + nt * 8 + lc * 2;
                int row0 = m0 + wm + mt * 16 + lr;
                int row1 = row0 + 8;
                if (row0 < M)
                    *reinterpret_cast<__half2*>(&g_projh[(size_t)row0 * 256 + col]) =
                        __floats2half2_rn(acc[mt][nt][0], acc[mt][nt][1]);
                if (row1 < M)
                    *reinterpret_cast<__half2*>(&g_projh[(size_t)row1 * 256 + col]) =
                        __floats2half2_rn(acc[mt][nt][2], acc[mt][nt][3]);
            }
        }
    } else {
#pragma unroll
        for (int mt = 0; mt < 2; mt++) {
#pragma unroll
            for (int nt = 0; nt < 8; nt++) {
                int col  = n0 + wn + nt * 8 + lc * 2;
                int row0 = m0 + wm + mt * 16 + lr;
                int row1 = row0 + 8;
                if (row0 < M)
                    *reinterpret_cast<float2*>(&outC[(size_t)row0 * 256 + col]) =
                        make_float2(acc[mt][nt][0], acc[mt][nt][1]);
                if (row1 < M)
                    *reinterpret_cast<float2*>(&outC[(size_t)row1 * 256 + col]) =
                        make_float2(acc[mt][nt][2], acc[mt][nt][3]);
            }
        }
    }

    // ---- fused attention-score epilogue (proj path only) ----
    if (is_proj) {
        const int head = (n0 + wn) >> 6;
        float asv[16], atv[16];
#pragma unroll
        for (int nt = 0; nt < 8; nt++)
#pragma unroll
            for (int i = 0; i < 2; i++) {
                int colh = nt * 8 + lc * 2 + i;
                asv[nt * 2 + i] = a_src[head * F + colh];
                atv[nt * 2 + i] = a_trg[head * F + colh];
            }
#pragma unroll
        for (int mt = 0; mt < 2; mt++)
#pragma unroll
            for (int rh = 0; rh < 2; rh++) {
                float ps = 0.f, pt = 0.f;
#pragma unroll
                for (int nt = 0; nt < 8; nt++)
#pragma unroll
                    for (int i = 0; i < 2; i++) {
                        float c = acc[mt][nt][rh * 2 + i];
                        ps = fmaf(c, asv[nt * 2 + i], ps);
                        pt = fmaf(c, atv[nt * 2 + i], pt);
                    }
                ps += __shfl_xor_sync(0xffffffffu, ps, 1);
                ps += __shfl_xor_sync(0xffffffffu, ps, 2);
                pt += __shfl_xor_sync(0xffffffffu, pt, 1);
                pt += __shfl_xor_sync(0xffffffffu, pt, 2);
                if (lc == 0) {
                    int row = m0 + wm + mt * 16 + lr + rh * 8;
                    if (row < M) {
                        g_ssrc[row * H + head] = ps;
                        g_strg[row * H + head] = pt;
                    }
                }
            }
    }
}

// -------- aggregation: fused exp + softmax + skip + bias + leaky ------------
// one warp per target node; lane owns 8 fp16 features = one 16B load/edge;
// 4-edge software pipeline for memory-level parallelism.
__device__ __forceinline__ float edge_ex(float ss, float st) {
    float v = ss + st;
    float e = (v > 0.0f) ? v : NEG * v;
    return expf(e);
}

__device__ __forceinline__ void acc8h(float* acc, uint4 q, float e) {
    float2 f;
    f = __half22float2(*reinterpret_cast<__half2*>(&q.x));
    acc[0] = fmaf(f.x, e, acc[0]); acc[1] = fmaf(f.y, e, acc[1]);
    f = __half22float2(*reinterpret_cast<__half2*>(&q.y));
    acc[2] = fmaf(f.x, e, acc[2]); acc[3] = fmaf(f.y, e, acc[3]);
    f = __half22float2(*reinterpret_cast<__half2*>(&q.z));
    acc[4] = fmaf(f.x, e, acc[4]); acc[5] = fmaf(f.y, e, acc[5]);
    f = __half22float2(*reinterpret_cast<__half2*>(&q.w));
    acc[6] = fmaf(f.x, e, acc[6]); acc[7] = fmaf(f.y, e, acc[7]);
}

__global__ void __launch_bounds__(256)
agg_kernel(float* __restrict__ out, const float* __restrict__ bias) {
    int n = (blockIdx.x * blockDim.x + threadIdx.x) >> 5;
    if (n >= N_NODES) return;
    int lane = threadIdx.x & 31;
    int h    = lane >> 3;

    float st  = g_strg[n * H + h];
    int   beg = g_off[n];
    int   end = g_off[n + 1];

    float acc[8];
#pragma unroll
    for (int i = 0; i < 8; i++) acc[i] = 0.0f;
    float den = 0.0f;

    int j = beg;
    for (; j + 4 <= end; j += 4) {
        int s0 = g_csr_src[j],     s1 = g_csr_src[j + 1];
        int s2 = g_csr_src[j + 2], s3 = g_csr_src[j + 3];
        float x0 = g_ssrc[s0 * H + h], x1 = g_ssrc[s1 * H + h];
        float x2 = g_ssrc[s2 * H + h], x3 = g_ssrc[s3 * H + h];
        uint4 q0 = *(reinterpret_cast<const uint4*>(g_projh + (size_t)s0 * HF) + lane);
        uint4 q1 = *(reinterpret_cast<const uint4*>(g_projh + (size_t)s1 * HF) + lane);
        uint4 q2 = *(reinterpret_cast<const uint4*>(g_projh + (size_t)s2 * HF) + lane);
        uint4 q3 = *(reinterpret_cast<const uint4*>(g_projh + (size_t)s3 * HF) + lane);
        float e0 = edge_ex(x0, st), e1 = edge_ex(x1, st);
        float e2 = edge_ex(x2, st), e3 = edge_ex(x3, st);
        den += (e0 + e1) + (e2 + e3);
        acc8h(acc, q0, e0);
        acc8h(acc, q1, e1);
        acc8h(acc, q2, e2);
        acc8h(acc, q3, e3);
    }
    for (; j < end; j++) {
        int   s  = g_csr_src[j];
        float ex = edge_ex(g_ssrc[s * H + h], st);
        den += ex;
        uint4 q = *(reinterpret_cast<const uint4*>(g_projh + (size_t)s * HF) + lane);
        acc8h(acc, q, ex);
    }

    float inv = 1.0f / (den + 1e-16f);
    float* o  = out + (size_t)n * HF + lane * 8;
    float4 s0 = *reinterpret_cast<const float4*>(o);
    float4 s1 = *reinterpret_cast<const float4*>(o + 4);
    const float4* bb = reinterpret_cast<const float4*>(bias) + lane * 2;
    float4 b0 = bb[0];
    float4 b1 = bb[1];

    float r[8];
    r[0] = acc[0] * inv + s0.x + b0.x;
    r[1] = acc[1] * inv + s0.y + b0.y;
    r[2] = acc[2] * inv + s0.z + b0.z;
    r[3] = acc[3] * inv + s0.w + b0.w;
    r[4] = acc[4] * inv + s1.x + b1.x;
    r[5] = acc[5] * inv + s1.y + b1.y;
    r[6] = acc[6] * inv + s1.z + b1.z;
    r[7] = acc[7] * inv + s1.w + b1.w;
#pragma unroll
    for (int i = 0; i < 8; i++) r[i] = (r[i] > 0.0f) ? r[i] : NEG * r[i];

    *reinterpret_cast<float4*>(o)     = make_float4(r[0], r[1], r[2], r[3]);
    *reinterpret_cast<float4*>(o + 4) = make_float4(r[4], r[5], r[6], r[7]);
}

// ---------------------------------------------------------------------------
extern "C" void kernel_launch(void* const* d_in, const int* in_sizes, int n_in,
                              void* d_out, int out_size) {
    const float* x      = (const float*)d_in[0];
    const float* W      = (const float*)d_in[1];
    const float* a_src  = (const float*)d_in[2];
    const float* a_trg  = (const float*)d_in[3];
    const float* skip_w = (const float*)d_in[4];
    const float* bias   = (const float*)d_in[5];
    const int*   esrc   = (const int*)d_in[6];
    const int*   etrg   = (const int*)d_in[7];
    float*       out    = (float*)d_out;

    static cudaStream_t s_csr = nullptr;
    static cudaEvent_t  ev_fork = nullptr, ev_join = nullptr;
    static void* deg_ptr = nullptr;
    if (!s_csr) {
        cudaStreamCreateWithFlags(&s_csr, cudaStreamNonBlocking);
        cudaEventCreateWithFlags(&ev_fork, cudaEventDisableTiming);
        cudaEventCreateWithFlags(&ev_join, cudaEventDisableTiming);
        cudaGetSymbolAddress(&deg_ptr, g_deg);
        cudaFuncSetAttribute(gemm_tf32_kernel,
                             cudaFuncAttributeMaxDynamicSharedMemorySize,
                             GEMM_SMEM);
    }

    // ---- fork: CSR build on side stream (hidden under the GEMM) ----
    cudaEventRecord(ev_fork, 0);
    cudaStreamWaitEvent(s_csr, ev_fork, 0);
    cudaMemsetAsync(deg_ptr, 0, N_NODES * sizeof(int), s_csr);
    count_kernel  <<<(N_EDGES + 255) / 256, 256, 0, s_csr>>>(etrg);
    scan_kernel   <<<1, SCAN_T, 0, s_csr>>>();
    scatter_kernel<<<(N_EDGES + 255) / 256, 256, 0, s_csr>>>(esrc, etrg);
    cudaEventRecord(ev_join, s_csr);

    // ---- main stream: fused GEMMs (+scores, fp16 proj) ----
    gemm_tf32_kernel<<<1564, 256, GEMM_SMEM>>>(x, W, skip_w, out,
                                               a_src, a_trg, N_NODES);

    // ---- join, then aggregate ----
    cudaStreamWaitEvent(0, ev_join, 0);
    agg_kernel<<<(N_NODES * 32 + 255) / 256, 256>>>(out, bias);
}

// round 17
// speedup vs baseline: 1.5555x; 1.5555x over previous
#include <cuda_runtime.h>
#include <cuda_fp16.h>
#include <cstdint>

// ---------------------------------------------------------------------------
// GAT layer. Fixed shapes: N=50000, E=800000, IN=256, H=4, F=64, HF=256
// Stream 0 : bcvt(B->tf32) -> gemm (cp.async double-buffered, pre-cvt B,
//            in-register tf32 cvt for A only, fused s_src/s_trg epilogue,
//            proj stored fp16) -> [wait CSR] -> agg (fused exp + softmax +
//            skip + bias + leaky, fp16 gather)
// Stream 2 : memset(deg) -> count -> scan -> scatter      (hidden under GEMM)
// ---------------------------------------------------------------------------

#define N_NODES 50000
#define N_EDGES 800000
#define IN_DIM  256
#define H       4
#define F       64
#define HF      256
#define NEG     0.2f

// -------- scratch (static device globals; allocation-free) -----------------
__device__ __half g_projh [N_NODES * HF];    // 25.6 MB, L2-resident in agg
__device__ float  g_ssrc  [N_NODES * H];
__device__ float  g_strg  [N_NODES * H];
__device__ float  g_Btf   [2 * 256 * 256];   // W and skip_w as tf32 bits
__device__ int    g_deg   [N_NODES];
__device__ int    g_off   [N_NODES + 1];
__device__ int    g_off2  [N_NODES];         // scatter cursor (starts = g_off)
__device__ int    g_csr_src[N_EDGES];

__device__ __forceinline__ unsigned f2tf32(float x) {
    unsigned r;
    asm("cvt.rna.tf32.f32 %0, %1;" : "=r"(r) : "f"(x));
    return r;
}

__device__ __forceinline__ uint32_t s2u(const void* p) {
    uint32_t a;
    asm("{ .reg .u64 t; cvta.to.shared.u64 t, %1; cvt.u32.u64 %0, t; }"
        : "=r"(a) : "l"(p));
    return a;
}

__device__ __forceinline__ void cp16(uint32_t dst, const void* src, int bytes) {
    asm volatile("cp.async.cg.shared.global [%0], [%1], 16, %2;"
                 :: "r"(dst), "l"(src), "r"(bytes));
}

__device__ __forceinline__ void mma_tf32(float* c,
                                         unsigned a0, unsigned a1,
                                         unsigned a2, unsigned a3,
                                         unsigned b0, unsigned b1) {
    asm volatile(
        "mma.sync.aligned.m16n8k8.row.col.f32.tf32.tf32.f32 "
        "{%0,%1,%2,%3}, {%4,%5,%6,%7}, {%8,%9}, {%0,%1,%2,%3};"
        : "+f"(c[0]), "+f"(c[1]), "+f"(c[2]), "+f"(c[3])
        : "r"(a0), "r"(a1), "r"(a2), "r"(a3), "r"(b0), "r"(b1));
}

// -------- B -> tf32 pre-conversion (4us, off the GEMM critical loop) --------
__global__ void __launch_bounds__(256)
bcvt_kernel(const float* __restrict__ W, const float* __restrict__ SW) {
    int i = blockIdx.x * 256 + threadIdx.x;           // 131072 total
    float v = (i < 65536) ? W[i] : SW[i - 65536];
    g_Btf[i] = __uint_as_float(f2tf32(v));
}

// -------- CSR build ---------------------------------------------------------
__global__ void __launch_bounds__(256)
count_kernel(const int* __restrict__ etrg) {
    int i = blockIdx.x * blockDim.x + threadIdx.x;
    if (i < N_EDGES) atomicAdd(&g_deg[etrg[i]], 1);
}

#define SCAN_T 1024
#define CHUNK  49
__global__ void __launch_bounds__(SCAN_T)
scan_kernel() {
    __shared__ int sm[SCAN_T];
    int t   = threadIdx.x;
    int beg = t * CHUNK;
    int end = min(beg + CHUNK, N_NODES);
    int s = 0;
    for (int i = beg; i < end; i++) s += g_deg[i];
    sm[t] = s;
    __syncthreads();
    for (int o = 1; o < SCAN_T; o <<= 1) {
        int v = (t >= o) ? sm[t - o] : 0;
        __syncthreads();
        if (t >= o) sm[t] += v;
        __syncthreads();
    }
    int base = (t > 0) ? sm[t - 1] : 0;
    for (int i = beg; i < end; i++) {
        g_off[i] = base; g_off2[i] = base; base += g_deg[i];
    }
    if (t == 0) g_off[N_NODES] = sm[SCAN_T - 1];
}

__global__ void __launch_bounds__(256)
scatter_kernel(const int* __restrict__ esrc, const int* __restrict__ etrg) {
    int i = blockIdx.x * blockDim.x + threadIdx.x;
    if (i >= N_EDGES) return;
    int pos = atomicAdd(&g_off2[etrg[i]], 1);
    g_csr_src[pos] = esrc[i];
}

// -------- TF32 MMA GEMM, cp.async double-buffered ---------------------------
// C[M,256] = A[M,256] @ B[256,256]; blockIdx.y in 0..3 selects (B,C,n-half).
// Block tile 128x128, BK=32, 8 warps (4 M x 2 N), warp tile 32x64.
// B comes pre-converted from g_Btf (raw bit loads in the inner loop);
// A staged raw fp32 and converted in-register at fragment load (8 CVT/kk).
// proj path stores fp16 and reduces s_src/s_trg from accumulator registers.
#define AS(p,m,k) As[(p)*4608 + (m)*36 + (k)]
#define BS(p,k,n) Bs[(p)*4352 + (k)*136 + (n)]
#define GEMM_SMEM ((2*4608 + 2*4352) * 4)

__global__ void __launch_bounds__(256, 2)
gemm_tf32_kernel(const float* __restrict__ A,
                 float* __restrict__ outC,
                 const float* __restrict__ a_src, const float* __restrict__ a_trg,
                 int M) {
    extern __shared__ float smf[];
    float* As = smf;
    float* Bs = smf + 2 * 4608;

    const bool is_proj = (blockIdx.y < 2);
    const float* Bt = g_Btf + (is_proj ? 0 : 65536);
    const int n0 = (blockIdx.y & 1) * 128;
    const int m0 = blockIdx.x * 128;

    const int t    = threadIdx.x;
    const int lane = t & 31;
    const int w    = t >> 5;
    const int wm   = (w & 3) * 32;
    const int wn   = (w >> 2) * 64;
    const int lr   = lane >> 2;
    const int lc   = lane & 3;

    float acc[2][8][4];
#pragma unroll
    for (int mt = 0; mt < 2; mt++)
#pragma unroll
        for (int nt = 0; nt < 8; nt++)
#pragma unroll
            for (int i = 0; i < 4; i++) acc[mt][nt][i] = 0.0f;

    // staging coords
    const int ar  = t >> 1;          // A row 0..127
    const int ac  = (t & 1) * 16;    // A k-offset
    const int br  = t >> 3;          // B k row 0..31
    const int bc0 = (t & 7) * 4;     // B n-offset, +32 strides

    const int      gm    = m0 + ar;
    const int      abyt  = (gm < M) ? 16 : 0;
    const float*   agp   = A + (size_t)gm * IN_DIM + ac;
    const uint32_t asm_b = s2u(&AS(0, ar, ac));
    const float*   bgp   = Bt + (size_t)br * 256 + n0 + bc0;
    const uint32_t bsm_b = s2u(&BS(0, br, bc0));

    // prologue: stage k0=0 into buffer 0
#pragma unroll
    for (int j = 0; j < 4; j++) cp16(asm_b + j * 16, agp + j * 4, abyt);
#pragma unroll
    for (int j = 0; j < 4; j++) cp16(bsm_b + j * 128, bgp + j * 32, 16);
    asm volatile("cp.async.commit_group;");

    int p = 0;
    for (int it = 0; it < 8; it++) {
        if (it < 7) {
            int k0 = (it + 1) * 32;
            uint32_t ad = asm_b + (p ^ 1) * 4608 * 4;
            uint32_t bd = bsm_b + (p ^ 1) * 4352 * 4;
#pragma unroll
            for (int j = 0; j < 4; j++) cp16(ad + j * 16,  agp + k0 + j * 4, abyt);
#pragma unroll
            for (int j = 0; j < 4; j++) cp16(bd + j * 128, bgp + (size_t)k0 * 256 + j * 32, 16);
            asm volatile("cp.async.commit_group;");
            asm volatile("cp.async.wait_group %0;" :: "n"(1));
        } else {
            asm volatile("cp.async.wait_group %0;" :: "n"(0));
        }
        __syncthreads();

#pragma unroll
        for (int kk = 0; kk < 32; kk += 8) {
            unsigned af[2][4], bf[8][2];
#pragma unroll
            for (int mt = 0; mt < 2; mt++) {
                int mb = wm + mt * 16;
                af[mt][0] = f2tf32(AS(p, mb + lr,     kk + lc));
                af[mt][1] = f2tf32(AS(p, mb + lr + 8, kk + lc));
                af[mt][2] = f2tf32(AS(p, mb + lr,     kk + lc + 4));
                af[mt][3] = f2tf32(AS(p, mb + lr + 8, kk + lc + 4));
            }
#pragma unroll
            for (int nt = 0; nt < 8; nt++) {
                int nb = wn + nt * 8 + lr;
                bf[nt][0] = __float_as_uint(BS(p, kk + lc,     nb));
                bf[nt][1] = __float_as_uint(BS(p, kk + lc + 4, nb));
            }
#pragma unroll
            for (int mt = 0; mt < 2; mt++)
#pragma unroll
                for (int nt = 0; nt < 8; nt++)
                    mma_tf32(acc[mt][nt],
                             af[mt][0], af[mt][1], af[mt][2], af[mt][3],
                             bf[nt][0], bf[nt][1]);
        }
        __syncthreads();
        p ^= 1;
    }

    // ---- store C: fp16 for proj, fp32 straight into out for skip ----
    if (is_proj) {
#pragma unroll
        for (int mt = 0; mt < 2; mt++) {
#pragma unroll
            for (int nt = 0; nt < 8; nt++) {
                int col  = n0 + wn + nt * 8 + lc * 2;
                int row0 = m0 + wm + mt * 16 + lr;
                int row1 = row0 + 8;
                if (row0 < M)
                    *reinterpret_cast<__half2*>(&g_projh[(size_t)row0 * 256 + col]) =
                        __floats2half2_rn(acc[mt][nt][0], acc[mt][nt][1]);
                if (row1 < M)
                    *reinterpret_cast<__half2*>(&g_projh[(size_t)row1 * 256 + col]) =
                        __floats2half2_rn(acc[mt][nt][2], acc[mt][nt][3]);
            }
        }
    } else {
#pragma unroll
        for (int mt = 0; mt < 2; mt++) {
#pragma unroll
            for (int nt = 0; nt < 8; nt++) {
                int col  = n0 + wn + nt * 8 + lc * 2;
                int row0 = m0 + wm + mt * 16 + lr;
                int row1 = row0 + 8;
                if (row0 < M)
                    *reinterpret_cast<float2*>(&outC[(size_t)row0 * 256 + col]) =
                        make_float2(acc[mt][nt][0], acc[mt][nt][1]);
                if (row1 < M)
                    *reinterpret_cast<float2*>(&outC[(size_t)row1 * 256 + col]) =
                        make_float2(acc[mt][nt][2], acc[mt][nt][3]);
            }
        }
    }

    // ---- fused attention-score epilogue (proj path only) ----
    if (is_proj) {
        const int head = (n0 + wn) >> 6;
        float asv[16], atv[16];
#pragma unroll
        for (int nt = 0; nt < 8; nt++)
#pragma unroll
            for (int i = 0; i < 2; i++) {
                int colh = nt * 8 + lc * 2 + i;
                asv[nt * 2 + i] = a_src[head * F + colh];
                atv[nt * 2 + i] = a_trg[head * F + colh];
            }
#pragma unroll
        for (int mt = 0; mt < 2; mt++)
#pragma unroll
            for (int rh = 0; rh < 2; rh++) {
                float ps = 0.f, pt = 0.f;
#pragma unroll
                for (int nt = 0; nt < 8; nt++)
#pragma unroll
                    for (int i = 0; i < 2; i++) {
                        float c = acc[mt][nt][rh * 2 + i];
                        ps = fmaf(c, asv[nt * 2 + i], ps);
                        pt = fmaf(c, atv[nt * 2 + i], pt);
                    }
                ps += __shfl_xor_sync(0xffffffffu, ps, 1);
                ps += __shfl_xor_sync(0xffffffffu, ps, 2);
                pt += __shfl_xor_sync(0xffffffffu, pt, 1);
                pt += __shfl_xor_sync(0xffffffffu, pt, 2);
                if (lc == 0) {
                    int row = m0 + wm + mt * 16 + lr + rh * 8;
                    if (row < M) {
                        g_ssrc[row * H + head] = ps;
                        g_strg[row * H + head] = pt;
                    }
                }
            }
    }
}

// -------- aggregation: fused exp + softmax + skip + bias + leaky ------------
// one warp per target node; lane owns 8 fp16 features = one 16B load/edge;
// 4-edge software pipeline for memory-level parallelism.
__device__ __forceinline__ float edge_ex(float ss, float st) {
    float v = ss + st;
    float e = (v > 0.0f) ? v : NEG * v;
    return expf(e);
}

__device__ __forceinline__ void acc8h(float* acc, uint4 q, float e) {
    float2 f;
    f = __half22float2(*reinterpret_cast<__half2*>(&q.x));
    acc[0] = fmaf(f.x, e, acc[0]); acc[1] = fmaf(f.y, e, acc[1]);
    f = __half22float2(*reinterpret_cast<__half2*>(&q.y));
    acc[2] = fmaf(f.x, e, acc[2]); acc[3] = fmaf(f.y, e, acc[3]);
    f = __half22float2(*reinterpret_cast<__half2*>(&q.z));
    acc[4] = fmaf(f.x, e, acc[4]); acc[5] = fmaf(f.y, e, acc[5]);
    f = __half22float2(*reinterpret_cast<__half2*>(&q.w));
    acc[6] = fmaf(f.x, e, acc[6]); acc[7] = fmaf(f.y, e, acc[7]);
}

__global__ void __launch_bounds__(256)
agg_kernel(float* __restrict__ out, const float* __restrict__ bias) {
    int n = (blockIdx.x * blockDim.x + threadIdx.x) >> 5;
    if (n >= N_NODES) return;
    int lane = threadIdx.x & 31;
    int h    = lane >> 3;

    float st  = g_strg[n * H + h];
    int   beg = g_off[n];
    int   end = g_off[n + 1];

    float acc[8];
#pragma unroll
    for (int i = 0; i < 8; i++) acc[i] = 0.0f;
    float den = 0.0f;

    int j = beg;
    for (; j + 4 <= end; j += 4) {
        int s0 = g_csr_src[j],     s1 = g_csr_src[j + 1];
        int s2 = g_csr_src[j + 2], s3 = g_csr_src[j + 3];
        float x0 = g_ssrc[s0 * H + h], x1 = g_ssrc[s1 * H + h];
        float x2 = g_ssrc[s2 * H + h], x3 = g_ssrc[s3 * H + h];
        uint4 q0 = *(reinterpret_cast<const uint4*>(g_projh + (size_t)s0 * HF) + lane);
        uint4 q1 = *(reinterpret_cast<const uint4*>(g_projh + (size_t)s1 * HF) + lane);
        uint4 q2 = *(reinterpret_cast<const uint4*>(g_projh + (size_t)s2 * HF) + lane);
        uint4 q3 = *(reinterpret_cast<const uint4*>(g_projh + (size_t)s3 * HF) + lane);
        float e0 = edge_ex(x0, st), e1 = edge_ex(x1, st);
        float e2 = edge_ex(x2, st), e3 = edge_ex(x3, st);
        den += (e0 + e1) + (e2 + e3);
        acc8h(acc, q0, e0);
        acc8h(acc, q1, e1);
        acc8h(acc, q2, e2);
        acc8h(acc, q3, e3);
    }
    for (; j < end; j++) {
        int   s  = g_csr_src[j];
        float ex = edge_ex(g_ssrc[s * H + h], st);
        den += ex;
        uint4 q = *(reinterpret_cast<const uint4*>(g_projh + (size_t)s * HF) + lane);
        acc8h(acc, q, ex);
    }

    float inv = 1.0f / (den + 1e-16f);
    float* o  = out + (size_t)n * HF + lane * 8;
    float4 s0 = *reinterpret_cast<const float4*>(o);
    float4 s1 = *reinterpret_cast<const float4*>(o + 4);
    const float4* bb = reinterpret_cast<const float4*>(bias) + lane * 2;
    float4 b0 = bb[0];
    float4 b1 = bb[1];

    float r[8];
    r[0] = acc[0] * inv + s0.x + b0.x;
    r[1] = acc[1] * inv + s0.y + b0.y;
    r[2] = acc[2] * inv + s0.z + b0.z;
    r[3] = acc[3] * inv + s0.w + b0.w;
    r[4] = acc[4] * inv + s1.x + b1.x;
    r[5] = acc[5] * inv + s1.y + b1.y;
    r[6] = acc[6] * inv + s1.z + b1.z;
    r[7] = acc[7] * inv + s1.w + b1.w;
#pragma unroll
    for (int i = 0; i < 8; i++) r[i] = (r[i] > 0.0f) ? r[i] : NEG * r[i];

    *reinterpret_cast<float4*>(o)     = make_float4(r[0], r[1], r[2], r[3]);
    *reinterpret_cast<float4*>(o + 4) = make_float4(r[4], r[5], r[6], r[7]);
}

// ---------------------------------------------------------------------------
extern "C" void kernel_launch(void* const* d_in, const int* in_sizes, int n_in,
                              void* d_out, int out_size) {
    const float* x      = (const float*)d_in[0];
    const float* W      = (const float*)d_in[1];
    const float* a_src  = (const float*)d_in[2];
    const float* a_trg  = (const float*)d_in[3];
    const float* skip_w = (const float*)d_in[4];
    const float* bias   = (const float*)d_in[5];
    const int*   esrc   = (const int*)d_in[6];
    const int*   etrg   = (const int*)d_in[7];
    float*       out    = (float*)d_out;

    static cudaStream_t s_csr = nullptr;
    static cudaEvent_t  ev_fork = nullptr, ev_join = nullptr;
    static void* deg_ptr = nullptr;
    if (!s_csr) {
        cudaStreamCreateWithFlags(&s_csr, cudaStreamNonBlocking);
        cudaEventCreateWithFlags(&ev_fork, cudaEventDisableTiming);
        cudaEventCreateWithFlags(&ev_join, cudaEventDisableTiming);
        cudaGetSymbolAddress(&deg_ptr, g_deg);
        cudaFuncSetAttribute(gemm_tf32_kernel,
                             cudaFuncAttributeMaxDynamicSharedMemorySize,
                             GEMM_SMEM);
    }

    // ---- fork: CSR build on side stream (hidden under the GEMM) ----
    cudaEventRecord(ev_fork, 0);
    cudaStreamWaitEvent(s_csr, ev_fork, 0);
    cudaMemsetAsync(deg_ptr, 0, N_NODES * sizeof(int), s_csr);
    count_kernel  <<<(N_EDGES + 255) / 256, 256, 0, s_csr>>>(etrg);
    scan_kernel   <<<1, SCAN_T, 0, s_csr>>>();
    scatter_kernel<<<(N_EDGES + 255) / 256, 256, 0, s_csr>>>(esrc, etrg);
    cudaEventRecord(ev_join, s_csr);

    // ---- main stream: B->tf32, fused GEMMs (+scores, fp16 proj) ----
    bcvt_kernel<<<512, 256>>>(W, skip_w);
    dim3 ggrid((N_NODES + 127) / 128, 4);
    gemm_tf32_kernel<<<ggrid, 256, GEMM_SMEM>>>(x, out, a_src, a_trg, N_NODES);

    // ---- join, then aggregate ----
    cudaStreamWaitEvent(0, ev_join, 0);
    agg_kernel<<<(N_NODES * 32 + 255) / 256, 256>>>(out, bias);
}